// round 2
// baseline (speedup 1.0000x reference)
#include <cuda_runtime.h>

// QGN_30219389895238: 4-gate single-qubit Rot circuit, expval |<0|psi>|^2.
//
// Algebraic reduction:
//   U = prod_g RZ(w_g) RY(t_g) RZ(p_g) acting on |0>.
// RZ(p0)|0> = global phase (drop). Trailing RZ(w3) diagonal -> |s0|^2 invariant
// (drop). Fuse RZ(p_{g+1})RZ(w_g) = RZ(c_g), c_g = p_{g+1}+w_g, and
// RZ(c) ~ (global phase) * diag(1, e^{ic}) = P(c).
// => psi ~ RY(t3) P(c2) RY(t2) P(c1) RY(t1) P(c0) RY(t0) |0>
// 7 sincos per row instead of 12.
//
// Index map (gate g, slot j): angle = w[6g+2j] + x[3g+j]*w[6g+2j+1]
//   t0 = w2 +x1*w3    t1 = w8 +x4*w9    t2 = w14+x7*w15   t3 = w20+x10*w21
//   c0 = (w6+x3*w7)+(w4+x2*w5)
//   c1 = (w12+x6*w13)+(w10+x5*w11)
//   c2 = (w18+x9*w19)+(w16+x8*w17)

__global__ __launch_bounds__(256) void qgn_kernel(
    const float4* __restrict__ x4,   // [B*3] float4  (= [B,12] float)
    const float*  __restrict__ w,    // [24]
    float* __restrict__ out,         // [B]
    int n)
{
    int i = blockIdx.x * blockDim.x + threadIdx.x;
    if (i >= n) return;

    const float4* w4 = reinterpret_cast<const float4*>(w);
    float4 wa = __ldg(w4 + 0);  // w0..w3
    float4 wb = __ldg(w4 + 1);  // w4..w7
    float4 wc = __ldg(w4 + 2);  // w8..w11
    float4 wd = __ldg(w4 + 3);  // w12..w15
    float4 we = __ldg(w4 + 4);  // w16..w19
    float4 wf = __ldg(w4 + 5);  // w20..w23

    // Row features (fully coalesced: warp covers 1536 contiguous bytes).
    float4 v0 = x4[3 * i + 0];  // x0..x3
    float4 v1 = x4[3 * i + 1];  // x4..x7
    float4 v2 = x4[3 * i + 2];  // x8..x11

    // Half-angles for RY gates.
    float ht0 = 0.5f * fmaf(v0.y, wa.w, wa.z);   // 0.5*(w2  + x1 *w3)
    float ht1 = 0.5f * fmaf(v1.x, wc.y, wc.x);   // 0.5*(w8  + x4 *w9)
    float ht2 = 0.5f * fmaf(v1.w, wd.w, wd.z);   // 0.5*(w14 + x7 *w15)
    float ht3 = 0.5f * fmaf(v2.z, wf.y, wf.x);   // 0.5*(w20 + x10*w21)

    // Fused inter-gate phases c_g = phi_{g+1} + omega_g.
    float c0 = fmaf(v0.w, wb.w, wb.z) + fmaf(v0.z, wb.y, wb.x);   // (w6+x3*w7)+(w4+x2*w5)
    float c1 = fmaf(v1.z, wd.y, wd.x) + fmaf(v1.y, wc.w, wc.z);   // (w12+x6*w13)+(w10+x5*w11)
    float c2 = fmaf(v2.y, we.w, we.z) + fmaf(v2.x, we.y, we.x);   // (w18+x9*w19)+(w16+x8*w17)

    float st, ct, sc, cc;

    // Gate 0: RY(t0) on |0> -> real state (cos, sin)
    __sincosf(ht0, &st, &ct);
    float a0 = ct, b0 = 0.0f;   // s0 = a0 + i b0
    float a1 = st, b1 = 0.0f;   // s1 = a1 + i b1

    // Gate 1: P(c0) then RY(t1)
    __sincosf(c0, &sc, &cc);
    {
        float na1 = a1 * cc - b1 * sc;
        float nb1 = a1 * sc + b1 * cc;
        __sincosf(ht1, &st, &ct);
        float ta0 = ct * a0 - st * na1;
        float tb0 = ct * b0 - st * nb1;
        a1 = st * a0 + ct * na1;
        b1 = st * b0 + ct * nb1;
        a0 = ta0; b0 = tb0;
    }

    // Gate 2: P(c1) then RY(t2)
    __sincosf(c1, &sc, &cc);
    {
        float na1 = a1 * cc - b1 * sc;
        float nb1 = a1 * sc + b1 * cc;
        __sincosf(ht2, &st, &ct);
        float ta0 = ct * a0 - st * na1;
        float tb0 = ct * b0 - st * nb1;
        a1 = st * a0 + ct * na1;
        b1 = st * b0 + ct * nb1;
        a0 = ta0; b0 = tb0;
    }

    // Gate 3: P(c2) then RY(t3) — only s0 needed afterwards.
    __sincosf(c2, &sc, &cc);
    {
        float na1 = a1 * cc - b1 * sc;
        float nb1 = a1 * sc + b1 * cc;
        __sincosf(ht3, &st, &ct);
        float ta0 = ct * a0 - st * na1;
        float tb0 = ct * b0 - st * nb1;
        a0 = ta0; b0 = tb0;
    }

    out[i] = a0 * a0 + b0 * b0;
}

extern "C" void kernel_launch(void* const* d_in, const int* in_sizes, int n_in,
                              void* d_out, int out_size)
{
    const float* x = (const float*)d_in[0];
    const float* w = (const float*)d_in[1];
    if (n_in >= 2 && in_sizes[0] == 24) {  // defensive: swapped order
        w = (const float*)d_in[0];
        x = (const float*)d_in[1];
    }
    int n = out_size;  // B rows
    int threads = 256;
    int blocks = (n + threads - 1) / threads;
    qgn_kernel<<<blocks, threads>>>(
        reinterpret_cast<const float4*>(x), w, (float*)d_out, n);
}

// round 3
// speedup vs baseline: 1.0730x; 1.0730x over previous
#include <cuda_runtime.h>

// QGN_30219389895238: 4-gate single-qubit Rot circuit, expval |<0|psi>|^2.
//
// Algebraic reduction (verified R2, rel_err 7e-7):
//   psi ~ RY(t3) P(c2) RY(t2) P(c1) RY(t1) P(c0) RY(t0) |0>
// with t_g = w[6g+2]+x[3g+1]*w[6g+3], c_g = phi_{g+1}+omega_g.
// 7 sincos per row instead of 12.
//
// R3: 2 rows per thread (i and i+T), 6 front-batched coalesced LDG.128 per
// thread to raise MLP and DRAM saturation; 2 independent sincos chains for ILP.

struct S2 { float a0, b0, a1, b1; };

__device__ __forceinline__ void gate_p_ry(S2& s, float c, float ht)
{
    float sc, cc, st, ct;
    __sincosf(c, &sc, &cc);
    float na1 = s.a1 * cc - s.b1 * sc;
    float nb1 = s.a1 * sc + s.b1 * cc;
    __sincosf(ht, &st, &ct);
    float ta0 = ct * s.a0 - st * na1;
    float tb0 = ct * s.b0 - st * nb1;
    s.a1 = st * s.a0 + ct * na1;
    s.b1 = st * s.b0 + ct * nb1;
    s.a0 = ta0; s.b0 = tb0;
}

__global__ __launch_bounds__(256) void qgn_kernel2(
    const float4* __restrict__ x4,   // [B*3] float4  (= [B,12] float)
    const float*  __restrict__ w,    // [24]
    float* __restrict__ out,         // [B]
    int T)                            // = B/2
{
    int i = blockIdx.x * blockDim.x + threadIdx.x;
    if (i >= T) return;
    int j = i + T;

    // Front-batch all 6 row loads (each LDG.128 warp-coalesced; MLP_p1 = 6).
    float4 r0a = x4[3 * i + 0];
    float4 r0b = x4[3 * i + 1];
    float4 r0c = x4[3 * i + 2];
    float4 r1a = x4[3 * j + 0];
    float4 r1b = x4[3 * j + 1];
    float4 r1c = x4[3 * j + 2];

    const float4* w4 = reinterpret_cast<const float4*>(w);
    float4 wa = __ldg(w4 + 0);  // w0..w3
    float4 wb = __ldg(w4 + 1);  // w4..w7
    float4 wc = __ldg(w4 + 2);  // w8..w11
    float4 wd = __ldg(w4 + 3);  // w12..w15
    float4 we = __ldg(w4 + 4);  // w16..w19
    float4 wf = __ldg(w4 + 5);  // w20..w23

    float res[2];
#pragma unroll
    for (int r = 0; r < 2; r++) {
        float4 v0 = r ? r1a : r0a;
        float4 v1 = r ? r1b : r0b;
        float4 v2 = r ? r1c : r0c;

        // Half-angles for RY gates.
        float ht0 = 0.5f * fmaf(v0.y, wa.w, wa.z);   // 0.5*(w2  + x1 *w3)
        float ht1 = 0.5f * fmaf(v1.x, wc.y, wc.x);   // 0.5*(w8  + x4 *w9)
        float ht2 = 0.5f * fmaf(v1.w, wd.w, wd.z);   // 0.5*(w14 + x7 *w15)
        float ht3 = 0.5f * fmaf(v2.z, wf.y, wf.x);   // 0.5*(w20 + x10*w21)

        // Fused inter-gate phases c_g = phi_{g+1} + omega_g.
        float c0 = fmaf(v0.w, wb.w, wb.z) + fmaf(v0.z, wb.y, wb.x);
        float c1 = fmaf(v1.z, wd.y, wd.x) + fmaf(v1.y, wc.w, wc.z);
        float c2 = fmaf(v2.y, we.w, we.z) + fmaf(v2.x, we.y, we.x);

        float st, ct;
        __sincosf(ht0, &st, &ct);
        S2 s{ct, 0.0f, st, 0.0f};
        gate_p_ry(s, c0, ht1);
        gate_p_ry(s, c1, ht2);
        gate_p_ry(s, c2, ht3);   // a1/b1 of last gate dead, compiler drops them
        res[r] = s.a0 * s.a0 + s.b0 * s.b0;
    }

    out[i] = res[0];
    out[j] = res[1];
}

extern "C" void kernel_launch(void* const* d_in, const int* in_sizes, int n_in,
                              void* d_out, int out_size)
{
    const float* x = (const float*)d_in[0];
    const float* w = (const float*)d_in[1];
    if (n_in >= 2 && in_sizes[0] == 24) {  // defensive: swapped order
        w = (const float*)d_in[0];
        x = (const float*)d_in[1];
    }
    int n = out_size;          // B rows (4194304, even)
    int T = n / 2;             // rows per half
    int threads = 256;
    int blocks = (T + threads - 1) / threads;
    qgn_kernel2<<<blocks, threads>>>(
        reinterpret_cast<const float4*>(x), w, (float*)d_out, T);
}

// round 4
// speedup vs baseline: 1.0846x; 1.0108x over previous
#include <cuda_runtime.h>

// QGN_30219389895238: 4-gate single-qubit Rot circuit, expval |<0|psi>|^2.
//
// Algebraic reduction (verified R2, rel_err 7e-7):
//   psi ~ RY(t3) P(c2) RY(t2) P(c1) RY(t1) P(c0) RY(t0) |0>
// with t_g = w[6g+2]+x[3g+1]*w[6g+3], c_g = phi_{g+1}+omega_g.
// 7 sincos per row instead of 12.
//
// R4: back to 1 row/thread (R3 showed MLP/ILP doesn't move the needle — kernel
// sits at the DRAM ceiling). Add streaming cache hints: __ldcs on the read-once
// feature stream, __stcs on the write-once output, to cut L2 retention churn.

__global__ __launch_bounds__(256) void qgn_kernel3(
    const float4* __restrict__ x4,   // [B*3] float4  (= [B,12] float)
    const float*  __restrict__ w,    // [24]
    float* __restrict__ out,         // [B]
    int n)
{
    int i = blockIdx.x * blockDim.x + threadIdx.x;
    if (i >= n) return;

    // Read-once feature stream: evict-first.
    float4 v0 = __ldcs(x4 + 3 * i + 0);  // x0..x3
    float4 v1 = __ldcs(x4 + 3 * i + 1);  // x4..x7
    float4 v2 = __ldcs(x4 + 3 * i + 2);  // x8..x11

    // Uniform weights: read-only cached broadcast.
    const float4* w4 = reinterpret_cast<const float4*>(w);
    float4 wa = __ldg(w4 + 0);  // w0..w3
    float4 wb = __ldg(w4 + 1);  // w4..w7
    float4 wc = __ldg(w4 + 2);  // w8..w11
    float4 wd = __ldg(w4 + 3);  // w12..w15
    float4 we = __ldg(w4 + 4);  // w16..w19
    float4 wf = __ldg(w4 + 5);  // w20..w23

    // Half-angles for RY gates.
    float ht0 = 0.5f * fmaf(v0.y, wa.w, wa.z);   // 0.5*(w2  + x1 *w3)
    float ht1 = 0.5f * fmaf(v1.x, wc.y, wc.x);   // 0.5*(w8  + x4 *w9)
    float ht2 = 0.5f * fmaf(v1.w, wd.w, wd.z);   // 0.5*(w14 + x7 *w15)
    float ht3 = 0.5f * fmaf(v2.z, wf.y, wf.x);   // 0.5*(w20 + x10*w21)

    // Fused inter-gate phases c_g = phi_{g+1} + omega_g.
    float c0 = fmaf(v0.w, wb.w, wb.z) + fmaf(v0.z, wb.y, wb.x);
    float c1 = fmaf(v1.z, wd.y, wd.x) + fmaf(v1.y, wc.w, wc.z);
    float c2 = fmaf(v2.y, we.w, we.z) + fmaf(v2.x, we.y, we.x);

    float st, ct, sc, cc;

    // Gate 0: RY(t0) on |0> -> real state.
    __sincosf(ht0, &st, &ct);
    float a0 = ct, b0 = 0.0f;   // s0 = a0 + i b0
    float a1 = st, b1 = 0.0f;   // s1 = a1 + i b1

    // Gate 1: P(c0) then RY(t1)
    __sincosf(c0, &sc, &cc);
    {
        float na1 = a1 * cc - b1 * sc;
        float nb1 = a1 * sc + b1 * cc;
        __sincosf(ht1, &st, &ct);
        float ta0 = ct * a0 - st * na1;
        float tb0 = ct * b0 - st * nb1;
        a1 = st * a0 + ct * na1;
        b1 = st * b0 + ct * nb1;
        a0 = ta0; b0 = tb0;
    }

    // Gate 2: P(c1) then RY(t2)
    __sincosf(c1, &sc, &cc);
    {
        float na1 = a1 * cc - b1 * sc;
        float nb1 = a1 * sc + b1 * cc;
        __sincosf(ht2, &st, &ct);
        float ta0 = ct * a0 - st * na1;
        float tb0 = ct * b0 - st * nb1;
        a1 = st * a0 + ct * na1;
        b1 = st * b0 + ct * nb1;
        a0 = ta0; b0 = tb0;
    }

    // Gate 3: P(c2) then RY(t3) — only s0 needed afterwards.
    __sincosf(c2, &sc, &cc);
    {
        float na1 = a1 * cc - b1 * sc;
        float nb1 = a1 * sc + b1 * cc;
        __sincosf(ht3, &st, &ct);
        float ta0 = ct * a0 - st * na1;
        float tb0 = ct * b0 - st * nb1;
        a0 = ta0; b0 = tb0;
    }

    // Write-once output: evict-first.
    __stcs(out + i, fmaf(a0, a0, b0 * b0));
}

extern "C" void kernel_launch(void* const* d_in, const int* in_sizes, int n_in,
                              void* d_out, int out_size)
{
    const float* x = (const float*)d_in[0];
    const float* w = (const float*)d_in[1];
    if (n_in >= 2 && in_sizes[0] == 24) {  // defensive: swapped order
        w = (const float*)d_in[0];
        x = (const float*)d_in[1];
    }
    int n = out_size;  // B rows
    int threads = 256;
    int blocks = (n + threads - 1) / threads;
    qgn_kernel3<<<blocks, threads>>>(
        reinterpret_cast<const float4*>(x), w, (float*)d_out, n);
}